// round 8
// baseline (speedup 1.0000x reference)
#include <cuda_runtime.h>
#include <cstdint>

// predictions [8,19,512,1024] f32, targets [8,512,1024] i32, output: scalar f32.
#define NB        8
#define NC        19
#define NPB       (512 * 1024)
#define THRESH    0.7f
#define NMIN      10000

#define TPB       256
#define TILE      256                          // pixels per tile (1 px / thread)
#define CH_BYTES  (TILE * 4)                   // 1024 B per channel chunk
#define TILE_BYTES ((NC + 1) * CH_BYTES)       // 19 ch + targets = 20480 B
#define CHUNKS    (TILE_BYTES / 16)            // 1280 x 16B chunks per tile
#define CPT       (CHUNKS / TPB)               // 5 chunks per thread
#define STAGES    2
#define TILES_PER_BATCH (NPB / TILE)           // 2048
#define BLK_PER_BATCH   74
#define GRID      (NB * BLK_PER_BATCH)         // 592  (4 blocks/SM target)

__device__ double       g_sum[NB];
__device__ int          g_cnt[NB];
__device__ unsigned int g_done;

// ---------------- PTX helpers ----------------
__device__ __forceinline__ uint32_t smem_u32(const void* p) {
    uint32_t a;
    asm("{ .reg .u64 t; cvta.to.shared.u64 t, %1; cvt.u32.u64 %0, t; }"
        : "=r"(a) : "l"(p));
    return a;
}
__device__ __forceinline__ void cp16(uint32_t dst, const void* src) {
    asm volatile("cp.async.cg.shared.global [%0], [%1], 16;"
                 :: "r"(dst), "l"(src) : "memory");
}
__device__ __forceinline__ void cp_commit() {
    asm volatile("cp.async.commit_group;" ::: "memory");
}
template <int N>
__device__ __forceinline__ void cp_wait() {
    asm volatile("cp.async.wait_group %0;" :: "n"(N) : "memory");
}

// CE loss recompute (rare exact-top-k fallback path only).
__device__ __forceinline__ float pixel_loss(const float* __restrict__ pred,
                                            const int*   __restrict__ tgt,
                                            int b, int i) {
    const int t = tgt[b * NPB + i];
    float s = 0.f, xt = 0.f;
#pragma unroll
    for (int c = 0; c < NC; c++) {
        const float v = pred[(b * NC + c) * NPB + i];
        s += __expf(v);
        if (c == t) xt = v;
    }
    float l = __logf(s) - xt;
    return l < 0.f ? 0.f : l;
}

extern __shared__ float sbuf[];   // STAGES * TILE_BYTES/4, 16B aligned

// Distributed fill of one stage with one tile (all 256 threads, 5 chunks each).
__device__ __forceinline__ void fill_tile(const float* __restrict__ pred,
                                          const int*   __restrict__ tgt,
                                          uint32_t sb, int stage,
                                          int b, int n /*pixel offset in batch*/,
                                          int tid) {
    const uint32_t dst0 = sb + stage * TILE_BYTES;
    const char* pbase = (const char*)(pred + (size_t)b * NC * NPB + n);
    const char* tbase = (const char*)(tgt + (size_t)b * NPB + n);
#pragma unroll
    for (int i = 0; i < CPT; i++) {
        const int j   = tid + i * TPB;          // chunk id 0..1279
        const int c   = j >> 6;                 // 64 chunks per 1KB row
        const int off = (j & 63) * 16;          // byte offset within row
        const char* src = (c < NC) ? (pbase + (size_t)c * NPB * 4 + off)
                                   : (tbase + off);
        cp16(dst0 + j * 16, src);
    }
    cp_commit();
}

__global__ void __launch_bounds__(TPB)
ohem_cpa(const float* __restrict__ pred,
         const int*   __restrict__ tgt,
         float*       __restrict__ out) {
    __shared__ float        sh_f[TPB / 32];
    __shared__ int          sh_i[TPB / 32];
    __shared__ unsigned int sh_last;

    const int tid  = threadIdx.x;
    const int w    = tid >> 5, lane = tid & 31;
    const uint32_t sb = smem_u32(sbuf);

    // Block -> (batch, local block index). 592 = 8 * 74, so batch is constant
    // per block and per-thread accumulators never mix batches.
    const int b  = blockIdx.x / BLK_PER_BATCH;
    const int jb = blockIdx.x % BLK_PER_BATCH;
    const int ntiles = (TILES_PER_BATCH - jb + BLK_PER_BATCH - 1) / BLK_PER_BATCH;

    float ls = 0.f;   // per-thread accumulation across ALL tiles
    int   lc = 0;

    // Prologue: tile 0 -> stage 0.
    fill_tile(pred, tgt, sb, 0, b, jb * TILE, tid);

    for (int k = 0; k < ntiles; k++) {
        const int stage = k & 1;
        if (k + 1 < ntiles) {
            fill_tile(pred, tgt, sb, stage ^ 1, b,
                      (jb + (k + 1) * BLK_PER_BATCH) * TILE, tid);
            cp_wait<1>();    // tile k complete (tile k+1 may be in flight)
        } else {
            cp_wait<0>();
        }
        __syncthreads();

        const float* buf = sbuf + stage * (TILE_BYTES / 4);

        float s0 = 0.f;
#pragma unroll
        for (int c = 0; c < NC; c++) s0 += __expf(buf[c * TILE + tid]);

        const int   t0 = reinterpret_cast<const int*>(buf + NC * TILE)[tid];
        const float l0 = __logf(s0) - buf[t0 * TILE + tid];
        if (l0 > THRESH) { ls += l0; lc++; }

        __syncthreads();   // everyone done reading before this stage refills
    }

    // One block reduction + one atomic pair for the whole block.
#pragma unroll
    for (int o = 16; o; o >>= 1) {
        ls += __shfl_down_sync(0xffffffffu, ls, o);
        lc += __shfl_down_sync(0xffffffffu, lc, o);
    }
    if (lane == 0) { sh_f[w] = ls; sh_i[w] = lc; }
    __syncthreads();
    if (tid == 0) {
        double S = 0.0; int Cn = 0;
#pragma unroll
        for (int i = 0; i < TPB / 32; i++) { S += (double)sh_f[i]; Cn += sh_i[i]; }
        atomicAdd(&g_sum[b], S);
        atomicAdd(&g_cnt[b], Cn);
        __threadfence();
        const unsigned int tk = atomicAdd(&g_done, 1u);
        sh_last = (tk == (unsigned)(GRID - 1)) ? 1u : 0u;
    }
    __syncthreads();
    if (!sh_last) return;

    // ---------------- finalize (last block) --------------------------------
    __threadfence();

    __shared__ unsigned int hist[256];
    __shared__ unsigned int s_prefix;
    __shared__ int          s_k;
    __shared__ double       sh_d2[TPB / 32];
    __shared__ int          sh_i2[TPB / 32];
    __shared__ double       s_acc;

    if (tid == 0) s_acc = 0.0;
    __syncthreads();

    for (int bb = 0; bb < NB; bb++) {
        const int    cnt = g_cnt[bb];
        const double sum = g_sum[bb];

        if (cnt >= NMIN) {
            if (tid == 0) s_acc += sum / (double)cnt;
            __syncthreads();
        } else {
            // Exact top-NMIN via 4-pass MSB radix select (dead on this input).
            if (tid == 0) { s_prefix = 0u; s_k = NMIN; }
            __syncthreads();
            for (int pass = 0; pass < 4; pass++) {
                const int shift = 24 - pass * 8;
                for (int i = tid; i < 256; i += TPB) hist[i] = 0u;
                __syncthreads();
                const unsigned prefix  = s_prefix;
                const unsigned mask_hi = (pass == 0) ? 0u
                                       : (0xFFFFFFFFu << (shift + 8));
                for (int i = tid; i < NPB; i += TPB) {
                    const unsigned u = __float_as_uint(pixel_loss(pred, tgt, bb, i));
                    if ((u & mask_hi) == prefix)
                        atomicAdd(&hist[(u >> shift) & 255u], 1u);
                }
                __syncthreads();
                if (tid == 0) {
                    int kk = s_k;
                    int d  = 255;
                    while (d > 0 && (int)hist[d] < kk) { kk -= (int)hist[d]; d--; }
                    s_prefix = prefix | ((unsigned)d << shift);
                    s_k      = kk;
                }
                __syncthreads();
            }
            const float pivot = __uint_as_float(s_prefix);
            double fs = 0.0; int fg = 0;
            for (int i = tid; i < NPB; i += TPB) {
                const float vv = pixel_loss(pred, tgt, bb, i);
                if (vv > pivot) { fs += (double)vv; fg++; }
            }
#pragma unroll
            for (int o = 16; o; o >>= 1) {
                fs += __shfl_down_sync(0xffffffffu, fs, o);
                fg += __shfl_down_sync(0xffffffffu, fg, o);
            }
            if (lane == 0) { sh_d2[w] = fs; sh_i2[w] = fg; }
            __syncthreads();
            if (tid == 0) {
                double S = 0.0; int G = 0;
#pragma unroll
                for (int i = 0; i < TPB / 32; i++) { S += sh_d2[i]; G += sh_i2[i]; }
                const double kept = S + (double)(NMIN - G) * (double)pivot;
                s_acc += kept / (double)NMIN;
            }
            __syncthreads();
        }
    }

    if (tid == 0) {
        out[0] = (float)(s_acc / (double)NB);
#pragma unroll
        for (int i = 0; i < NB; i++) { g_sum[i] = 0.0; g_cnt[i] = 0; }
        g_done = 0u;
        __threadfence();
    }
}

extern "C" void kernel_launch(void* const* d_in, const int* in_sizes, int n_in,
                              void* d_out, int out_size) {
    const float* pred = (const float*)d_in[0];
    const int*   tgt  = (const int*)d_in[1];
    float*       out  = (float*)d_out;

    static int smem_set = 0;
    if (!smem_set) {
        cudaFuncSetAttribute(ohem_cpa,
                             cudaFuncAttributeMaxDynamicSharedMemorySize,
                             STAGES * TILE_BYTES);
        smem_set = 1;
    }
    ohem_cpa<<<GRID, TPB, STAGES * TILE_BYTES>>>(pred, tgt, out);
}

// round 9
// speedup vs baseline: 1.0508x; 1.0508x over previous
#include <cuda_runtime.h>
#include <cstdint>

// predictions [8,19,512,1024] f32, targets [8,512,1024] i32, output: scalar f32.
#define NB        8
#define NC        19
#define NPB       (512 * 1024)
#define THRESH    0.7f
#define NMIN      10000

#define TPB       256
#define WARPS     (TPB / 32)
#define TILE_W    32                       // pixels per warp-tile (1 px / lane)
#define ROW_B     128                      // bytes per channel row (32 px * 4B)
#define W_BYTES   ((NC + 1) * ROW_B)       // 2560 B per warp-tile
#define W_CHUNKS  (W_BYTES / 16)           // 160 x 16B
#define CPL       (W_CHUNKS / 32)          // 5 chunks per lane
#define STAGES    4
#define BLK_PER_BATCH 37
#define GRID      (NB * BLK_PER_BATCH)     // 296 (2 blocks/SM)
#define WPB       (BLK_PER_BATCH * WARPS)  // 296 warps per batch
#define TILES_PB  (NPB / TILE_W)           // 16384 warp-tiles per batch

__device__ double       g_sum[NB];
__device__ int          g_cnt[NB];
__device__ unsigned int g_done;

// ---------------- PTX helpers ----------------
__device__ __forceinline__ uint32_t smem_u32(const void* p) {
    uint32_t a;
    asm("{ .reg .u64 t; cvta.to.shared.u64 t, %1; cvt.u32.u64 %0, t; }"
        : "=r"(a) : "l"(p));
    return a;
}
__device__ __forceinline__ void cp16(uint32_t dst, const void* src) {
    asm volatile("cp.async.cg.shared.global [%0], [%1], 16;"
                 :: "r"(dst), "l"(src) : "memory");
}
__device__ __forceinline__ void cp_commit() {
    asm volatile("cp.async.commit_group;" ::: "memory");
}
template <int N>
__device__ __forceinline__ void cp_wait() {
    asm volatile("cp.async.wait_group %0;" :: "n"(N) : "memory");
}

// CE loss recompute (rare exact-top-k fallback path only).
__device__ __forceinline__ float pixel_loss(const float* __restrict__ pred,
                                            const int*   __restrict__ tgt,
                                            int b, int i) {
    const int t = tgt[b * NPB + i];
    float s = 0.f, xt = 0.f;
#pragma unroll
    for (int c = 0; c < NC; c++) {
        const float v = pred[(b * NC + c) * NPB + i];
        s += __expf(v);
        if (c == t) xt = v;
    }
    float l = __logf(s) - xt;
    return l < 0.f ? 0.f : l;
}

extern __shared__ float sbuf[];   // WARPS * STAGES * W_BYTES, 16B aligned

// One warp fills one of its private stages with a 32-pixel tile.
__device__ __forceinline__ void fill_warp_tile(const float* __restrict__ pred,
                                               const int*   __restrict__ tgt,
                                               uint32_t dst, int b, int n,
                                               int lane) {
    const char* pbase = (const char*)(pred + (size_t)b * NC * NPB + n);
    const char* tbase = (const char*)(tgt + (size_t)b * NPB + n);
#pragma unroll
    for (int i = 0; i < CPL; i++) {
        const int j   = lane + i * 32;          // chunk 0..159
        const int c   = j >> 3;                 // 8 chunks per 128B row
        const int off = (j & 7) * 16;
        const char* src = (c < NC) ? (pbase + (size_t)c * NPB * 4 + off)
                                   : (tbase + off);
        cp16(dst + j * 16, src);
    }
    cp_commit();
}

__global__ void __launch_bounds__(TPB)
ohem_warp(const float* __restrict__ pred,
          const int*   __restrict__ tgt,
          float*       __restrict__ out) {
    __shared__ float        sh_f[WARPS];
    __shared__ int          sh_i[WARPS];
    __shared__ unsigned int sh_last;

    const int tid  = threadIdx.x;
    const int wid  = tid >> 5, lane = tid & 31;
    const uint32_t sb    = smem_u32(sbuf);
    const uint32_t wbase = sb + wid * (STAGES * W_BYTES);

    // Block -> (batch, warp-in-batch). 296 = 8 * 37 keeps batch block-pure.
    const int b  = blockIdx.x / BLK_PER_BATCH;
    const int jb = blockIdx.x % BLK_PER_BATCH;
    const int wb = jb * WARPS + wid;           // 0..295 within batch
    const int ntiles = (TILES_PB - wb + WPB - 1) / WPB;

    // Prologue: fill up to 3 tiles ahead (warp-private, no block sync).
#pragma unroll
    for (int s = 0; s < STAGES - 1; s++)
        if (s < ntiles)
            fill_warp_tile(pred, tgt, wbase + s * W_BYTES, b,
                           (wb + s * WPB) * TILE_W, lane);

    float ls = 0.f;
    int   lc = 0;

    for (int k = 0; k < ntiles; k++) {
        cp_wait<STAGES - 2>();   // tile k's group complete
        __syncwarp();            // cross-lane visibility + reconvergence

        const float* buf = sbuf + (wid * STAGES + (k & (STAGES - 1)))
                                  * (W_BYTES / 4);
        float s0 = 0.f;
#pragma unroll
        for (int c = 0; c < NC; c++) s0 += __expf(buf[c * 32 + lane]);

        const int   t0 = reinterpret_cast<const int*>(buf)[NC * 32 + lane];
        const float l0 = __logf(s0) - buf[t0 * 32 + lane];
        if (l0 > THRESH) { ls += l0; lc++; }

        // Refill the stage consumed at iter k-1 (safe: top-of-loop syncwarp
        // ordered every lane's k-1 reads before any lane's new cp.async).
        if (k + STAGES - 1 < ntiles)
            fill_warp_tile(pred, tgt,
                           wbase + ((k + STAGES - 1) & (STAGES - 1)) * W_BYTES,
                           b, (wb + (k + STAGES - 1) * WPB) * TILE_W, lane);
    }

    // Single block reduction + one atomic pair at the very end.
#pragma unroll
    for (int o = 16; o; o >>= 1) {
        ls += __shfl_down_sync(0xffffffffu, ls, o);
        lc += __shfl_down_sync(0xffffffffu, lc, o);
    }
    if (lane == 0) { sh_f[wid] = ls; sh_i[wid] = lc; }
    __syncthreads();
    if (tid == 0) {
        double S = 0.0; int Cn = 0;
#pragma unroll
        for (int i = 0; i < WARPS; i++) { S += (double)sh_f[i]; Cn += sh_i[i]; }
        atomicAdd(&g_sum[b], S);
        atomicAdd(&g_cnt[b], Cn);
        __threadfence();
        const unsigned int tk = atomicAdd(&g_done, 1u);
        sh_last = (tk == (unsigned)(GRID - 1)) ? 1u : 0u;
    }
    __syncthreads();
    if (!sh_last) return;

    // ---------------- finalize (last block) --------------------------------
    __threadfence();

    __shared__ unsigned int hist[256];
    __shared__ unsigned int s_prefix;
    __shared__ int          s_k;
    __shared__ double       sh_d2[WARPS];
    __shared__ int          sh_i2[WARPS];
    __shared__ double       s_acc;

    if (tid == 0) s_acc = 0.0;
    __syncthreads();

    for (int bb = 0; bb < NB; bb++) {
        const int    cnt = g_cnt[bb];
        const double sum = g_sum[bb];

        if (cnt >= NMIN) {
            if (tid == 0) s_acc += sum / (double)cnt;
            __syncthreads();
        } else {
            // Exact top-NMIN via 4-pass MSB radix select (dead on this input).
            if (tid == 0) { s_prefix = 0u; s_k = NMIN; }
            __syncthreads();
            for (int pass = 0; pass < 4; pass++) {
                const int shift = 24 - pass * 8;
                for (int i = tid; i < 256; i += TPB) hist[i] = 0u;
                __syncthreads();
                const unsigned prefix  = s_prefix;
                const unsigned mask_hi = (pass == 0) ? 0u
                                       : (0xFFFFFFFFu << (shift + 8));
                for (int i = tid; i < NPB; i += TPB) {
                    const unsigned u = __float_as_uint(pixel_loss(pred, tgt, bb, i));
                    if ((u & mask_hi) == prefix)
                        atomicAdd(&hist[(u >> shift) & 255u], 1u);
                }
                __syncthreads();
                if (tid == 0) {
                    int kk = s_k;
                    int d  = 255;
                    while (d > 0 && (int)hist[d] < kk) { kk -= (int)hist[d]; d--; }
                    s_prefix = prefix | ((unsigned)d << shift);
                    s_k      = kk;
                }
                __syncthreads();
            }
            const float pivot = __uint_as_float(s_prefix);
            double fs = 0.0; int fg = 0;
            for (int i = tid; i < NPB; i += TPB) {
                const float vv = pixel_loss(pred, tgt, bb, i);
                if (vv > pivot) { fs += (double)vv; fg++; }
            }
#pragma unroll
            for (int o = 16; o; o >>= 1) {
                fs += __shfl_down_sync(0xffffffffu, fs, o);
                fg += __shfl_down_sync(0xffffffffu, fg, o);
            }
            if (lane == 0) { sh_d2[wid] = fs; sh_i2[wid] = fg; }
            __syncthreads();
            if (tid == 0) {
                double S = 0.0; int G = 0;
#pragma unroll
                for (int i = 0; i < WARPS; i++) { S += sh_d2[i]; G += sh_i2[i]; }
                const double kept = S + (double)(NMIN - G) * (double)pivot;
                s_acc += kept / (double)NMIN;
            }
            __syncthreads();
        }
    }

    if (tid == 0) {
        out[0] = (float)(s_acc / (double)NB);
#pragma unroll
        for (int i = 0; i < NB; i++) { g_sum[i] = 0.0; g_cnt[i] = 0; }
        g_done = 0u;
        __threadfence();
    }
}

extern "C" void kernel_launch(void* const* d_in, const int* in_sizes, int n_in,
                              void* d_out, int out_size) {
    const float* pred = (const float*)d_in[0];
    const int*   tgt  = (const int*)d_in[1];
    float*       out  = (float*)d_out;

    static int smem_set = 0;
    if (!smem_set) {
        cudaFuncSetAttribute(ohem_warp,
                             cudaFuncAttributeMaxDynamicSharedMemorySize,
                             WARPS * STAGES * W_BYTES);
        smem_set = 1;
    }
    ohem_warp<<<GRID, TPB, WARPS * STAGES * W_BYTES>>>(pred, tgt, out);
}